// round 4
// baseline (speedup 1.0000x reference)
#include <cuda_runtime.h>
#include <cuda_bf16.h>
#include <cstdint>
#include <cstddef>

// ---------------------------------------------------------------------------
// MultiLatentAttention — B=4, T=4096, C=2048, H=16, D=128, L=64, CHUNK=128
// Key insight: causal mask t<=l with L=64 < CHUNK=128 means only the first
// 128 tokens ever feed the latent attention. K/V GEMMs shrink to M=512.
// Pipeline:
//   1) k128 = x[:, :128] @ Wk      (tf32 mma GEMM, 512x2048x2048)
//   2) v128 = x[:, :128] @ Wv
//   3) glogits = x @ Wg            (16384x1024x2048)
//   4) gates = softmax(glogits * SCALE) over L      (in-place)
//   5) attn  = per-(b,h) rope(k)->scores->masked chunk-0 softmax->@v
//   6) weighted[b,t,h,d] = sum_l attn[b,h,l,d]*gates[b,t,h,l]
//   7) out = weighted @ Wp         (16384x2048x2048)
// ---------------------------------------------------------------------------

#define SCALE_F 0.08838834764831845f  // 1/sqrt(128)

// Scratch (device globals — no allocation allowed)
__device__ float g_k128[512 * 2048];
__device__ float g_v128[512 * 2048];
__device__ float g_gates[16384 * 1024];
__device__ float g_attn[64 * 64 * 128];
__device__ float g_weighted[16384 * 2048];

__device__ __forceinline__ float ftf32(float x) {
    uint32_t u;
    asm("cvt.rna.tf32.f32 %0, %1;" : "=r"(u) : "f"(x));
    return __uint_as_float(u);
}

// ---------------------------------------------------------------------------
// TF32 GEMM: C[M,N] = A[M,K] @ B[K,N], all row-major fp32 in gmem.
// Logical A-row r maps to physical row (r/P)*Q + (r%P)  (for the x[:, :128]
// sub-view; P=M, Q=0 gives identity).
// Block tile 128x128x32, 8 warps, warp tile 32x64, mma.m16n8k8.tf32.
// ---------------------------------------------------------------------------
#define AST 36    // A smem row stride (floats)
#define BST 132   // B smem row stride (floats)

__global__ __launch_bounds__(256, 1)
void gemm_tf32(const float* __restrict__ A, const float* __restrict__ B,
               float* __restrict__ C, int M, int N, int K, int P, int Q) {
    __shared__ float As[128 * AST];
    __shared__ float Bs[32 * BST];

    const int tid  = threadIdx.x;
    const int bm   = blockIdx.y, bn = blockIdx.x;
    const int warp = tid >> 5, lane = tid & 31;
    const int wm   = warp & 3, wn = warp >> 2;   // 4 x 2 warp grid
    const int g    = lane >> 2, tg = lane & 3;

    float acc[2][8][4];
#pragma unroll
    for (int mt = 0; mt < 2; ++mt)
#pragma unroll
        for (int nt = 0; nt < 8; ++nt)
#pragma unroll
            for (int i = 0; i < 4; ++i) acc[mt][nt][i] = 0.0f;

    // Precompute mapped A rows for this thread's 4 float4 loads (k-independent)
    int arows[4];
    int acols[4];
    int brows[4];
    int bcols[4];
#pragma unroll
    for (int it = 0; it < 4; ++it) {
        int idx4 = tid + it * 256;
        int ar   = idx4 >> 3;              // 0..127
        acols[it] = (idx4 & 7) << 2;       // 0..28
        int r    = bm * 128 + ar;
        arows[it] = (r / P) * Q + (r % P);
        brows[it] = idx4 >> 5;             // 0..31
        bcols[it] = (idx4 & 31) << 2;      // 0..124
    }

    float4 aR[4], bR[4];
    const int KT = K >> 5;  // K/32

    // Prologue: load tile kt=0
#pragma unroll
    for (int it = 0; it < 4; ++it) {
        aR[it] = *(const float4*)(A + (size_t)arows[it] * K + acols[it]);
        bR[it] = *(const float4*)(B + (size_t)brows[it] * N + bn * 128 + bcols[it]);
    }
#pragma unroll
    for (int it = 0; it < 4; ++it) {
        int idx4 = tid + it * 256;
        float4 v = aR[it];
        *(float4*)&As[(idx4 >> 3) * AST + acols[it]] =
            make_float4(ftf32(v.x), ftf32(v.y), ftf32(v.z), ftf32(v.w));
        float4 u = bR[it];
        *(float4*)&Bs[brows[it] * BST + bcols[it]] =
            make_float4(ftf32(u.x), ftf32(u.y), ftf32(u.z), ftf32(u.w));
    }
    __syncthreads();

    for (int kt = 0; kt < KT; ++kt) {
        // Prefetch next gmem tile into registers
        if (kt + 1 < KT) {
            int k0 = (kt + 1) << 5;
#pragma unroll
            for (int it = 0; it < 4; ++it) {
                aR[it] = *(const float4*)(A + (size_t)arows[it] * K + k0 + acols[it]);
                bR[it] = *(const float4*)(B + (size_t)(k0 + brows[it]) * N + bn * 128 + bcols[it]);
            }
        }

        // Compute 4 k-slices of 8 from smem.
        // k-permutation trick: logical k index tg holds physical k=2tg, logical
        // tg+4 holds physical 2tg+1 — applied identically to A and B fragments,
        // so the dot product is unchanged and A fragments load as float2.
#pragma unroll
        for (int ks = 0; ks < 4; ++ks) {
            const int kk = ks << 3;
            float a0[2], a1[2], a2[2], a3[2];
#pragma unroll
            for (int mt = 0; mt < 2; ++mt) {
                int r0 = wm * 32 + mt * 16 + g;
                float2 p  = *(const float2*)&As[r0 * AST + kk + 2 * tg];
                float2 q2 = *(const float2*)&As[(r0 + 8) * AST + kk + 2 * tg];
                a0[mt] = p.x; a2[mt] = p.y; a1[mt] = q2.x; a3[mt] = q2.y;
            }
            float b0[8], b1[8];
#pragma unroll
            for (int nt = 0; nt < 8; ++nt) {
                int c = wn * 64 + nt * 8 + g;
                b0[nt] = Bs[(kk + 2 * tg) * BST + c];
                b1[nt] = Bs[(kk + 2 * tg + 1) * BST + c];
            }
#pragma unroll
            for (int mt = 0; mt < 2; ++mt)
#pragma unroll
                for (int nt = 0; nt < 8; ++nt) {
                    float* d = acc[mt][nt];
                    asm volatile(
                        "mma.sync.aligned.m16n8k8.row.col.f32.tf32.tf32.f32 "
                        "{%0,%1,%2,%3}, {%4,%5,%6,%7}, {%8,%9}, {%0,%1,%2,%3};\n"
                        : "+f"(d[0]), "+f"(d[1]), "+f"(d[2]), "+f"(d[3])
                        : "r"(__float_as_uint(a0[mt])), "r"(__float_as_uint(a1[mt])),
                          "r"(__float_as_uint(a2[mt])), "r"(__float_as_uint(a3[mt])),
                          "r"(__float_as_uint(b0[nt])), "r"(__float_as_uint(b1[nt])));
                }
        }
        __syncthreads();
        if (kt + 1 < KT) {
#pragma unroll
            for (int it = 0; it < 4; ++it) {
                int idx4 = tid + it * 256;
                float4 v = aR[it];
                *(float4*)&As[(idx4 >> 3) * AST + acols[it]] =
                    make_float4(ftf32(v.x), ftf32(v.y), ftf32(v.z), ftf32(v.w));
                float4 u = bR[it];
                *(float4*)&Bs[brows[it] * BST + bcols[it]] =
                    make_float4(ftf32(u.x), ftf32(u.y), ftf32(u.z), ftf32(u.w));
            }
            __syncthreads();
        }
    }

    // Epilogue
#pragma unroll
    for (int mt = 0; mt < 2; ++mt) {
        int row = bm * 128 + wm * 32 + mt * 16 + g;
#pragma unroll
        for (int nt = 0; nt < 8; ++nt) {
            int col = bn * 128 + wn * 64 + nt * 8 + 2 * tg;
            float2 v0 = make_float2(acc[mt][nt][0], acc[mt][nt][1]);
            float2 v1 = make_float2(acc[mt][nt][2], acc[mt][nt][3]);
            *(float2*)(C + (size_t)row * N + col)       = v0;
            *(float2*)(C + (size_t)(row + 8) * N + col) = v1;
        }
    }
}

// ---------------------------------------------------------------------------
// Gates softmax (in-place): rows = B*T*H = 262144, width L = 64.
// One warp per row, 8 rows per 256-thread block.
// ---------------------------------------------------------------------------
__global__ void gates_softmax(float* __restrict__ gbuf) {
    const int warp = threadIdx.x >> 5, lane = threadIdx.x & 31;
    size_t row = (size_t)blockIdx.x * 8 + warp;
    float* p = gbuf + row * 64;
    float a = p[lane] * SCALE_F;
    float b = p[lane + 32] * SCALE_F;
    float m = fmaxf(a, b);
#pragma unroll
    for (int o = 16; o > 0; o >>= 1) m = fmaxf(m, __shfl_xor_sync(0xffffffffu, m, o));
    float ea = expf(a - m), eb = expf(b - m);
    float s = ea + eb;
#pragma unroll
    for (int o = 16; o > 0; o >>= 1) s += __shfl_xor_sync(0xffffffffu, s, o);
    float inv = 1.0f / s;
    p[lane]      = ea * inv;
    p[lane + 32] = eb * inv;
}

// ---------------------------------------------------------------------------
// Latent attention (chunk 0 only): per (b,h) block.
// RoPE(k) -> scores(q,k)*SCALE, mask t>l -> chunk softmax -> attn = w @ v.
// Dynamic smem: q[64][128] + k[128][132] + w[64][128]
// ---------------------------------------------------------------------------
#define ATTN_SMEM_FLOATS (64 * 128 + 128 * 132 + 64 * 128)
#define ATTN_SMEM_BYTES (ATTN_SMEM_FLOATS * 4)

__global__ __launch_bounds__(256)
void attn_kernel(const float* __restrict__ k128, const float* __restrict__ v128,
                 const float* __restrict__ lq, float* __restrict__ attn_out) {
    extern __shared__ float sm[];
    float* q_s = sm;                  // [64][128]
    float* k_s = sm + 64 * 128;       // [128][132]
    float* w_s = k_s + 128 * 132;     // [64][128]

    const int tid = threadIdx.x;
    const int bh = blockIdx.x;
    const int b = bh >> 4, h = bh & 15;

    // Load latent queries: q[l][d] = lq[(l*16 + h)*128 + d]
    for (int i = tid; i < 64 * 128; i += 256) {
        int l = i >> 7, d = i & 127;
        q_s[i] = lq[((size_t)l * 16 + h) * 128 + d];
    }
    // Load K rows 0..127 with RoPE applied. Pairs are consecutive lanes.
    const float LOG2_THETA_OVER_HALF = 0.20762050593643188f;  // log2(10000)/64
    for (int p = tid; p < 128 * 64; p += 256) {
        int t = p >> 6, i = p & 63;
        const float* kp = k128 + ((size_t)(b * 128 + t)) * 2048 + h * 128 + 2 * i;
        float x0 = kp[0], x1 = kp[1];
        float invf = exp2f(-(float)i * LOG2_THETA_OVER_HALF);
        float ang = (float)t * invf;
        float sn, cs;
        sincosf(ang, &sn, &cs);
        k_s[t * 132 + 2 * i]     = x0 * cs - x1 * sn;
        k_s[t * 132 + 2 * i + 1] = x0 * sn + x1 * cs;
    }
    __syncthreads();

    // Scores: thread (t = tid&127, lb = tid>>7) covers l = lb, lb+2, ...
    {
        const int t = tid & 127, lb = tid >> 7;
        const float4* kv = (const float4*)(k_s + t * 132);
        for (int j = 0; j < 32; ++j) {
            int l = lb + 2 * j;
            const float4* qv = (const float4*)(q_s + l * 128);
            float s = 0.0f;
#pragma unroll
            for (int dd = 0; dd < 32; ++dd) {
                float4 a = qv[dd];
                float4 kk = kv[dd];
                s += a.x * kk.x + a.y * kk.y + a.z * kk.z + a.w * kk.w;
            }
            s *= SCALE_F;
            if (t > l) s = -1e9f;
            w_s[l * 128 + t] = s;
        }
    }
    __syncthreads();

    // Per-row softmax over the 128-token chunk (matches ref: max-sub, exp, norm)
    {
        const int warp = tid >> 5, lane = tid & 31;
        for (int r = 0; r < 8; ++r) {
            int l = warp * 8 + r;
            float v0 = w_s[l * 128 + lane];
            float v1 = w_s[l * 128 + lane + 32];
            float v2 = w_s[l * 128 + lane + 64];
            float v3 = w_s[l * 128 + lane + 96];
            float m = fmaxf(fmaxf(v0, v1), fmaxf(v2, v3));
#pragma unroll
            for (int o = 16; o > 0; o >>= 1) m = fmaxf(m, __shfl_xor_sync(0xffffffffu, m, o));
            float e0 = expf(v0 - m), e1 = expf(v1 - m), e2 = expf(v2 - m), e3 = expf(v3 - m);
            float s = e0 + e1 + e2 + e3;
#pragma unroll
            for (int o = 16; o > 0; o >>= 1) s += __shfl_xor_sync(0xffffffffu, s, o);
            float inv = 1.0f / s;
            w_s[l * 128 + lane]      = e0 * inv;
            w_s[l * 128 + lane + 32] = e1 * inv;
            w_s[l * 128 + lane + 64] = e2 * inv;
            w_s[l * 128 + lane + 96] = e3 * inv;
        }
    }
    __syncthreads();

    // attn[l][d] = sum_t w[l][t] * v[t][d]
    {
        const int d = tid & 127, lb = tid >> 7;
        float acc[32];
#pragma unroll
        for (int j = 0; j < 32; ++j) acc[j] = 0.0f;
        for (int t = 0; t < 128; ++t) {
            float vv = v128[((size_t)(b * 128 + t)) * 2048 + h * 128 + d];
#pragma unroll
            for (int j = 0; j < 32; ++j) acc[j] += w_s[(lb + 2 * j) * 128 + t] * vv;
        }
#pragma unroll
        for (int j = 0; j < 32; ++j)
            attn_out[((size_t)bh * 64 + lb + 2 * j) * 128 + d] = acc[j];
    }
}

// ---------------------------------------------------------------------------
// weighted[b,t,h,d] = sum_l attn[b,h,l,d] * gates[b,t,h,l]
// Block: one (b,h) x 32-token tile. Output layout [B*T, H*D] row-major.
// ---------------------------------------------------------------------------
__global__ __launch_bounds__(256)
void weighted_kernel(const float* __restrict__ attn, const float* __restrict__ gates,
                     float* __restrict__ wout) {
    __shared__ float a_s[64 * 128];  // attn[l][d]
    __shared__ float g_s[32 * 64];   // gates[t][l] for this tile

    const int tid = threadIdx.x;
    const int bh = blockIdx.y;
    const int b = bh >> 4, h = bh & 15;
    const int tb = blockIdx.x * 32;

    for (int i = tid; i < 64 * 128; i += 256)
        a_s[i] = attn[(size_t)bh * 8192 + i];
    for (int i = tid; i < 32 * 64; i += 256) {
        int tt = i >> 6, l = i & 63;
        g_s[i] = gates[(((size_t)(b * 4096) + tb + tt) * 16 + h) * 64 + l];
    }
    __syncthreads();

    const int dq = (tid & 31) * 4;  // 4 consecutive d per thread
    const int tr = tid >> 5;        // 8 t-rows, x4 j -> 32 t
    float acc[4][4];
#pragma unroll
    for (int j = 0; j < 4; ++j)
#pragma unroll
        for (int i = 0; i < 4; ++i) acc[j][i] = 0.0f;

    for (int l = 0; l < 64; ++l) {
        float4 av = *(const float4*)(a_s + l * 128 + dq);
#pragma unroll
        for (int j = 0; j < 4; ++j) {
            float gv = g_s[(tr + 8 * j) * 64 + l];
            acc[j][0] += gv * av.x;
            acc[j][1] += gv * av.y;
            acc[j][2] += gv * av.z;
            acc[j][3] += gv * av.w;
        }
    }
#pragma unroll
    for (int j = 0; j < 4; ++j) {
        int t = tb + tr + 8 * j;
        float4 v = make_float4(acc[j][0], acc[j][1], acc[j][2], acc[j][3]);
        *(float4*)(wout + (((size_t)(b * 4096) + t) * 16 + h) * 128 + dq) = v;
    }
}

// ---------------------------------------------------------------------------
extern "C" void kernel_launch(void* const* d_in, const int* in_sizes, int n_in,
                              void* d_out, int out_size) {
    const float* x  = (const float*)d_in[0];  // [4,4096,2048]
    const float* lq = (const float*)d_in[1];  // [1,64,16,128]
    const float* Wk = (const float*)d_in[2];  // [2048,2048]
    const float* Wv = (const float*)d_in[3];  // [2048,2048]
    const float* Wg = (const float*)d_in[4];  // [2048,1024]
    const float* Wp = (const float*)d_in[5];  // [2048,2048]
    float* out = (float*)d_out;

    float *kb, *vb, *gb, *ab, *wb;
    cudaGetSymbolAddress((void**)&kb, g_k128);
    cudaGetSymbolAddress((void**)&vb, g_v128);
    cudaGetSymbolAddress((void**)&gb, g_gates);
    cudaGetSymbolAddress((void**)&ab, g_attn);
    cudaGetSymbolAddress((void**)&wb, g_weighted);

    cudaFuncSetAttribute(attn_kernel, cudaFuncAttributeMaxDynamicSharedMemorySize,
                         ATTN_SMEM_BYTES);

    // 1/2: K,V for the first 128 tokens of each batch (row map: (r/128)*4096 + r%128)
    gemm_tf32<<<dim3(2048 / 128, 512 / 128), 256>>>(x, Wk, kb, 512, 2048, 2048, 128, 4096);
    gemm_tf32<<<dim3(2048 / 128, 512 / 128), 256>>>(x, Wv, vb, 512, 2048, 2048, 128, 4096);
    // 3: gate logits (identity row map)
    gemm_tf32<<<dim3(1024 / 128, 16384 / 128), 256>>>(x, Wg, gb, 16384, 1024, 2048, 16384, 0);
    // 4: gates softmax (in-place)
    gates_softmax<<<262144 / 8, 256>>>(gb);
    // 5: latent attention (rope + masked chunk-0 softmax + @v)
    attn_kernel<<<64, 256, ATTN_SMEM_BYTES>>>(kb, vb, lq, ab);
    // 6: gate-weighted mixing -> weighted [B*T, 2048]
    weighted_kernel<<<dim3(4096 / 32, 64), 256>>>(ab, gb, wb);
    // 7: output projection
    gemm_tf32<<<dim3(2048 / 128, 16384 / 128), 256>>>(wb, Wp, out, 16384, 2048, 2048, 16384, 0);
}

// round 5
// speedup vs baseline: 1.0021x; 1.0021x over previous
#include <cuda_runtime.h>
#include <cuda_bf16.h>
#include <cstdint>
#include <cstddef>

// ---------------------------------------------------------------------------
// MultiLatentAttention — B=4, T=4096, C=2048, H=16, D=128, L=64, CHUNK=128
// Key insight: causal mask t<=l with L=64 < CHUNK=128 means only the first
// 128 tokens ever feed the latent attention. K/V GEMMs shrink to M=512.
// Pipeline:
//   1) k128 = x[:, :128] @ Wk      (tf32 mma GEMM, 512x2048x2048)
//   2) v128 = x[:, :128] @ Wv
//   3) glogits = x @ Wg            (16384x1024x2048)
//   4) gates = softmax(glogits * SCALE) over L      (in-place)
//   5) attn  = per-(b,h) rope(k)->scores->masked chunk-0 softmax->@v
//   6) weighted[b,t,h,d] = sum_l attn[b,h,l,d]*gates[b,t,h,l]
//   7) out = weighted @ Wp         (16384x2048x2048)
// ---------------------------------------------------------------------------

#define SCALE_F 0.08838834764831845f  // 1/sqrt(128)

// Scratch (device globals — no allocation allowed)
__device__ float g_k128[512 * 2048];
__device__ float g_v128[512 * 2048];
__device__ float g_gates[16384 * 1024];
__device__ float g_attn[64 * 64 * 128];
__device__ float g_weighted[16384 * 2048];

__device__ __forceinline__ float ftf32(float x) {
    uint32_t u;
    asm("cvt.rna.tf32.f32 %0, %1;" : "=r"(u) : "f"(x));
    return __uint_as_float(u);
}

// ---------------------------------------------------------------------------
// TF32 GEMM: C[M,N] = A[M,K] @ B[K,N], all row-major fp32 in gmem.
// Logical A-row r maps to physical row (r/P)*Q + (r%P)  (for the x[:, :128]
// sub-view; P=M, Q=0 gives identity).
// Block tile 128x128x32, 8 warps, warp tile 32x64, mma.m16n8k8.tf32.
// ---------------------------------------------------------------------------
#define AST 36    // A smem row stride (floats)
#define BST 132   // B smem row stride (floats)

__global__ __launch_bounds__(256, 1)
void gemm_tf32(const float* __restrict__ A, const float* __restrict__ B,
               float* __restrict__ C, int M, int N, int K, int P, int Q) {
    __shared__ float As[128 * AST];
    __shared__ float Bs[32 * BST];

    const int tid  = threadIdx.x;
    const int bm   = blockIdx.y, bn = blockIdx.x;
    const int warp = tid >> 5, lane = tid & 31;
    const int wm   = warp & 3, wn = warp >> 2;   // 4 x 2 warp grid
    const int g    = lane >> 2, tg = lane & 3;

    float acc[2][8][4];
#pragma unroll
    for (int mt = 0; mt < 2; ++mt)
#pragma unroll
        for (int nt = 0; nt < 8; ++nt)
#pragma unroll
            for (int i = 0; i < 4; ++i) acc[mt][nt][i] = 0.0f;

    // Precompute mapped A rows for this thread's 4 float4 loads (k-independent)
    int arows[4];
    int acols[4];
    int brows[4];
    int bcols[4];
#pragma unroll
    for (int it = 0; it < 4; ++it) {
        int idx4 = tid + it * 256;
        int ar   = idx4 >> 3;              // 0..127
        acols[it] = (idx4 & 7) << 2;       // 0..28
        int r    = bm * 128 + ar;
        arows[it] = (r / P) * Q + (r % P);
        brows[it] = idx4 >> 5;             // 0..31
        bcols[it] = (idx4 & 31) << 2;      // 0..124
    }

    float4 aR[4], bR[4];
    const int KT = K >> 5;  // K/32

    // Prologue: load tile kt=0
#pragma unroll
    for (int it = 0; it < 4; ++it) {
        aR[it] = *(const float4*)(A + (size_t)arows[it] * K + acols[it]);
        bR[it] = *(const float4*)(B + (size_t)brows[it] * N + bn * 128 + bcols[it]);
    }
#pragma unroll
    for (int it = 0; it < 4; ++it) {
        int idx4 = tid + it * 256;
        float4 v = aR[it];
        *(float4*)&As[(idx4 >> 3) * AST + acols[it]] =
            make_float4(ftf32(v.x), ftf32(v.y), ftf32(v.z), ftf32(v.w));
        float4 u = bR[it];
        *(float4*)&Bs[brows[it] * BST + bcols[it]] =
            make_float4(ftf32(u.x), ftf32(u.y), ftf32(u.z), ftf32(u.w));
    }
    __syncthreads();

    for (int kt = 0; kt < KT; ++kt) {
        // Prefetch next gmem tile into registers
        if (kt + 1 < KT) {
            int k0 = (kt + 1) << 5;
#pragma unroll
            for (int it = 0; it < 4; ++it) {
                aR[it] = *(const float4*)(A + (size_t)arows[it] * K + k0 + acols[it]);
                bR[it] = *(const float4*)(B + (size_t)(k0 + brows[it]) * N + bn * 128 + bcols[it]);
            }
        }

        // Compute 4 k-slices of 8 from smem.
        // k-permutation trick: logical k index tg holds physical k=2tg, logical
        // tg+4 holds physical 2tg+1 — applied identically to A and B fragments,
        // so the dot product is unchanged and A fragments load as float2.
#pragma unroll
        for (int ks = 0; ks < 4; ++ks) {
            const int kk = ks << 3;
            float a0[2], a1[2], a2[2], a3[2];
#pragma unroll
            for (int mt = 0; mt < 2; ++mt) {
                int r0 = wm * 32 + mt * 16 + g;
                float2 p  = *(const float2*)&As[r0 * AST + kk + 2 * tg];
                float2 q2 = *(const float2*)&As[(r0 + 8) * AST + kk + 2 * tg];
                a0[mt] = p.x; a2[mt] = p.y; a1[mt] = q2.x; a3[mt] = q2.y;
            }
            float b0[8], b1[8];
#pragma unroll
            for (int nt = 0; nt < 8; ++nt) {
                int c = wn * 64 + nt * 8 + g;
                b0[nt] = Bs[(kk + 2 * tg) * BST + c];
                b1[nt] = Bs[(kk + 2 * tg + 1) * BST + c];
            }
#pragma unroll
            for (int mt = 0; mt < 2; ++mt)
#pragma unroll
                for (int nt = 0; nt < 8; ++nt) {
                    float* d = acc[mt][nt];
                    asm volatile(
                        "mma.sync.aligned.m16n8k8.row.col.f32.tf32.tf32.f32 "
                        "{%0,%1,%2,%3}, {%4,%5,%6,%7}, {%8,%9}, {%0,%1,%2,%3};\n"
                        : "+f"(d[0]), "+f"(d[1]), "+f"(d[2]), "+f"(d[3])
                        : "r"(__float_as_uint(a0[mt])), "r"(__float_as_uint(a1[mt])),
                          "r"(__float_as_uint(a2[mt])), "r"(__float_as_uint(a3[mt])),
                          "r"(__float_as_uint(b0[nt])), "r"(__float_as_uint(b1[nt])));
                }
        }
        __syncthreads();
        if (kt + 1 < KT) {
#pragma unroll
            for (int it = 0; it < 4; ++it) {
                int idx4 = tid + it * 256;
                float4 v = aR[it];
                *(float4*)&As[(idx4 >> 3) * AST + acols[it]] =
                    make_float4(ftf32(v.x), ftf32(v.y), ftf32(v.z), ftf32(v.w));
                float4 u = bR[it];
                *(float4*)&Bs[brows[it] * BST + bcols[it]] =
                    make_float4(ftf32(u.x), ftf32(u.y), ftf32(u.z), ftf32(u.w));
            }
            __syncthreads();
        }
    }

    // Epilogue
#pragma unroll
    for (int mt = 0; mt < 2; ++mt) {
        int row = bm * 128 + wm * 32 + mt * 16 + g;
#pragma unroll
        for (int nt = 0; nt < 8; ++nt) {
            int col = bn * 128 + wn * 64 + nt * 8 + 2 * tg;
            float2 v0 = make_float2(acc[mt][nt][0], acc[mt][nt][1]);
            float2 v1 = make_float2(acc[mt][nt][2], acc[mt][nt][3]);
            *(float2*)(C + (size_t)row * N + col)       = v0;
            *(float2*)(C + (size_t)(row + 8) * N + col) = v1;
        }
    }
}

// ---------------------------------------------------------------------------
// Gates softmax (in-place): rows = B*T*H = 262144, width L = 64.
// One warp per row, 8 rows per 256-thread block.
// ---------------------------------------------------------------------------
__global__ void gates_softmax(float* __restrict__ gbuf) {
    const int warp = threadIdx.x >> 5, lane = threadIdx.x & 31;
    size_t row = (size_t)blockIdx.x * 8 + warp;
    float* p = gbuf + row * 64;
    float a = p[lane] * SCALE_F;
    float b = p[lane + 32] * SCALE_F;
    float m = fmaxf(a, b);
#pragma unroll
    for (int o = 16; o > 0; o >>= 1) m = fmaxf(m, __shfl_xor_sync(0xffffffffu, m, o));
    float ea = expf(a - m), eb = expf(b - m);
    float s = ea + eb;
#pragma unroll
    for (int o = 16; o > 0; o >>= 1) s += __shfl_xor_sync(0xffffffffu, s, o);
    float inv = 1.0f / s;
    p[lane]      = ea * inv;
    p[lane + 32] = eb * inv;
}

// ---------------------------------------------------------------------------
// Latent attention (chunk 0 only): per (b,h) block.
// RoPE(k) -> scores(q,k)*SCALE, mask t>l -> chunk softmax -> attn = w @ v.
// Dynamic smem: q[64][128] + k[128][132] + w[64][128]
// ---------------------------------------------------------------------------
#define ATTN_SMEM_FLOATS (64 * 128 + 128 * 132 + 64 * 128)
#define ATTN_SMEM_BYTES (ATTN_SMEM_FLOATS * 4)

__global__ __launch_bounds__(256)
void attn_kernel(const float* __restrict__ k128, const float* __restrict__ v128,
                 const float* __restrict__ lq, float* __restrict__ attn_out) {
    extern __shared__ float sm[];
    float* q_s = sm;                  // [64][128]
    float* k_s = sm + 64 * 128;       // [128][132]
    float* w_s = k_s + 128 * 132;     // [64][128]

    const int tid = threadIdx.x;
    const int bh = blockIdx.x;
    const int b = bh >> 4, h = bh & 15;

    // Load latent queries: q[l][d] = lq[(l*16 + h)*128 + d]
    for (int i = tid; i < 64 * 128; i += 256) {
        int l = i >> 7, d = i & 127;
        q_s[i] = lq[((size_t)l * 16 + h) * 128 + d];
    }
    // Load K rows 0..127 with RoPE applied. Pairs are consecutive lanes.
    const float LOG2_THETA_OVER_HALF = 0.20762050593643188f;  // log2(10000)/64
    for (int p = tid; p < 128 * 64; p += 256) {
        int t = p >> 6, i = p & 63;
        const float* kp = k128 + ((size_t)(b * 128 + t)) * 2048 + h * 128 + 2 * i;
        float x0 = kp[0], x1 = kp[1];
        float invf = exp2f(-(float)i * LOG2_THETA_OVER_HALF);
        float ang = (float)t * invf;
        float sn, cs;
        sincosf(ang, &sn, &cs);
        k_s[t * 132 + 2 * i]     = x0 * cs - x1 * sn;
        k_s[t * 132 + 2 * i + 1] = x0 * sn + x1 * cs;
    }
    __syncthreads();

    // Scores: thread (t = tid&127, lb = tid>>7) covers l = lb, lb+2, ...
    {
        const int t = tid & 127, lb = tid >> 7;
        const float4* kv = (const float4*)(k_s + t * 132);
        for (int j = 0; j < 32; ++j) {
            int l = lb + 2 * j;
            const float4* qv = (const float4*)(q_s + l * 128);
            float s = 0.0f;
#pragma unroll
            for (int dd = 0; dd < 32; ++dd) {
                float4 a = qv[dd];
                float4 kk = kv[dd];
                s += a.x * kk.x + a.y * kk.y + a.z * kk.z + a.w * kk.w;
            }
            s *= SCALE_F;
            if (t > l) s = -1e9f;
            w_s[l * 128 + t] = s;
        }
    }
    __syncthreads();

    // Per-row softmax over the 128-token chunk (matches ref: max-sub, exp, norm)
    {
        const int warp = tid >> 5, lane = tid & 31;
        for (int r = 0; r < 8; ++r) {
            int l = warp * 8 + r;
            float v0 = w_s[l * 128 + lane];
            float v1 = w_s[l * 128 + lane + 32];
            float v2 = w_s[l * 128 + lane + 64];
            float v3 = w_s[l * 128 + lane + 96];
            float m = fmaxf(fmaxf(v0, v1), fmaxf(v2, v3));
#pragma unroll
            for (int o = 16; o > 0; o >>= 1) m = fmaxf(m, __shfl_xor_sync(0xffffffffu, m, o));
            float e0 = expf(v0 - m), e1 = expf(v1 - m), e2 = expf(v2 - m), e3 = expf(v3 - m);
            float s = e0 + e1 + e2 + e3;
#pragma unroll
            for (int o = 16; o > 0; o >>= 1) s += __shfl_xor_sync(0xffffffffu, s, o);
            float inv = 1.0f / s;
            w_s[l * 128 + lane]      = e0 * inv;
            w_s[l * 128 + lane + 32] = e1 * inv;
            w_s[l * 128 + lane + 64] = e2 * inv;
            w_s[l * 128 + lane + 96] = e3 * inv;
        }
    }
    __syncthreads();

    // attn[l][d] = sum_t w[l][t] * v[t][d]
    {
        const int d = tid & 127, lb = tid >> 7;
        float acc[32];
#pragma unroll
        for (int j = 0; j < 32; ++j) acc[j] = 0.0f;
        for (int t = 0; t < 128; ++t) {
            float vv = v128[((size_t)(b * 128 + t)) * 2048 + h * 128 + d];
#pragma unroll
            for (int j = 0; j < 32; ++j) acc[j] += w_s[(lb + 2 * j) * 128 + t] * vv;
        }
#pragma unroll
        for (int j = 0; j < 32; ++j)
            attn_out[((size_t)bh * 64 + lb + 2 * j) * 128 + d] = acc[j];
    }
}

// ---------------------------------------------------------------------------
// weighted[b,t,h,d] = sum_l attn[b,h,l,d] * gates[b,t,h,l]
// Block: one (b,h) x 32-token tile. Output layout [B*T, H*D] row-major.
// ---------------------------------------------------------------------------
__global__ __launch_bounds__(256)
void weighted_kernel(const float* __restrict__ attn, const float* __restrict__ gates,
                     float* __restrict__ wout) {
    __shared__ float a_s[64 * 128];  // attn[l][d]
    __shared__ float g_s[32 * 64];   // gates[t][l] for this tile

    const int tid = threadIdx.x;
    const int bh = blockIdx.y;
    const int b = bh >> 4, h = bh & 15;
    const int tb = blockIdx.x * 32;

    for (int i = tid; i < 64 * 128; i += 256)
        a_s[i] = attn[(size_t)bh * 8192 + i];
    for (int i = tid; i < 32 * 64; i += 256) {
        int tt = i >> 6, l = i & 63;
        g_s[i] = gates[(((size_t)(b * 4096) + tb + tt) * 16 + h) * 64 + l];
    }
    __syncthreads();

    const int dq = (tid & 31) * 4;  // 4 consecutive d per thread
    const int tr = tid >> 5;        // 8 t-rows, x4 j -> 32 t
    float acc[4][4];
#pragma unroll
    for (int j = 0; j < 4; ++j)
#pragma unroll
        for (int i = 0; i < 4; ++i) acc[j][i] = 0.0f;

    for (int l = 0; l < 64; ++l) {
        float4 av = *(const float4*)(a_s + l * 128 + dq);
#pragma unroll
        for (int j = 0; j < 4; ++j) {
            float gv = g_s[(tr + 8 * j) * 64 + l];
            acc[j][0] += gv * av.x;
            acc[j][1] += gv * av.y;
            acc[j][2] += gv * av.z;
            acc[j][3] += gv * av.w;
        }
    }
#pragma unroll
    for (int j = 0; j < 4; ++j) {
        int t = tb + tr + 8 * j;
        float4 v = make_float4(acc[j][0], acc[j][1], acc[j][2], acc[j][3]);
        *(float4*)(wout + (((size_t)(b * 4096) + t) * 16 + h) * 128 + dq) = v;
    }
}

// ---------------------------------------------------------------------------
extern "C" void kernel_launch(void* const* d_in, const int* in_sizes, int n_in,
                              void* d_out, int out_size) {
    const float* x  = (const float*)d_in[0];  // [4,4096,2048]
    const float* lq = (const float*)d_in[1];  // [1,64,16,128]
    const float* Wk = (const float*)d_in[2];  // [2048,2048]
    const float* Wv = (const float*)d_in[3];  // [2048,2048]
    const float* Wg = (const float*)d_in[4];  // [2048,1024]
    const float* Wp = (const float*)d_in[5];  // [2048,2048]
    float* out = (float*)d_out;

    float *kb, *vb, *gb, *ab, *wb;
    cudaGetSymbolAddress((void**)&kb, g_k128);
    cudaGetSymbolAddress((void**)&vb, g_v128);
    cudaGetSymbolAddress((void**)&gb, g_gates);
    cudaGetSymbolAddress((void**)&ab, g_attn);
    cudaGetSymbolAddress((void**)&wb, g_weighted);

    cudaFuncSetAttribute(attn_kernel, cudaFuncAttributeMaxDynamicSharedMemorySize,
                         ATTN_SMEM_BYTES);

    // 1/2: K,V for the first 128 tokens of each batch (row map: (r/128)*4096 + r%128)
    gemm_tf32<<<dim3(2048 / 128, 512 / 128), 256>>>(x, Wk, kb, 512, 2048, 2048, 128, 4096);
    gemm_tf32<<<dim3(2048 / 128, 512 / 128), 256>>>(x, Wv, vb, 512, 2048, 2048, 128, 4096);
    // 3: gate logits (identity row map)
    gemm_tf32<<<dim3(1024 / 128, 16384 / 128), 256>>>(x, Wg, gb, 16384, 1024, 2048, 16384, 0);
    // 4: gates softmax (in-place)
    gates_softmax<<<262144 / 8, 256>>>(gb);
    // 5: latent attention (rope + masked chunk-0 softmax + @v)
    attn_kernel<<<64, 256, ATTN_SMEM_BYTES>>>(kb, vb, lq, ab);
    // 6: gate-weighted mixing -> weighted [B*T, 2048]
    weighted_kernel<<<dim3(4096 / 32, 64), 256>>>(ab, gb, wb);
    // 7: output projection
    gemm_tf32<<<dim3(2048 / 128, 16384 / 128), 256>>>(wb, Wp, out, 16384, 2048, 2048, 16384, 0);
}

// round 11
// speedup vs baseline: 4.1829x; 4.1740x over previous
#include <cuda_runtime.h>
#include <cuda_fp16.h>
#include <cstdint>
#include <cstddef>

// ---------------------------------------------------------------------------
// MultiLatentAttention — B=4, T=4096, C=2048, H=16, D=128, L=64, CHUNK=128
// Only the first 128 tokens per batch feed the latent attention (mask t<=l).
// Reassociated epilogue: AP[b,h] = attn[b,h] @ Wp_h (2.2GF), out = gates@AP
// (68.7GF) replaces weighted+outGEMM (141.7GF). All big GEMMs run fp16
// m16n8k16 mma with ldmatrix + 3-stage cp.async (tcgen05 unavailable: the
// harness emits compute_103 PTX which rejects arch-specific instructions).
// ---------------------------------------------------------------------------

#define SCALE_F 0.08838834764831845f  // 1/sqrt(128)

__device__ __half g_x16[16384 * 2048];     // x rounded to fp16
__device__ __half g_wkvT[4096 * 2048];     // [Wk^T ; Wv^T] fp16, [N][K]
__device__ __half g_wgT[1024 * 2048];      // Wg^T fp16
__device__ float  g_kv128[512 * 4096];     // k (cols 0..2047) | v (2048..4095)
__device__ float  g_glog[16384 * 1024];    // gate logits fp32
__device__ __half g_gates16[16384 * 1024]; // softmaxed gates fp16
__device__ float  g_attn[64 * 64 * 128];   // attn[bh][l][d]
__device__ __half g_APt[4 * 2048 * 1024];  // per-batch (attn@Wp)^T: [n][h*64+l]

// single dynamic-smem symbol for the whole TU
extern __shared__ char dyn_sm[];

__device__ __forceinline__ uint32_t s2u(const void* p) {
    uint32_t a;
    asm("{ .reg .u64 t; cvta.to.shared.u64 t, %1; cvt.u32.u64 %0, t; }" : "=r"(a) : "l"(p));
    return a;
}
__device__ __forceinline__ void cp16(uint32_t dst, const void* src) {
    asm volatile("cp.async.cg.shared.global [%0], [%1], 16;" :: "r"(dst), "l"(src));
}
#define CP_COMMIT() asm volatile("cp.async.commit_group;" ::: "memory")
#define CP_WAIT2()  asm volatile("cp.async.wait_group 2;" ::: "memory")

#define LDSM4(r, addr)                                                        \
    asm volatile("ldmatrix.sync.aligned.m8n8.x4.shared.b16 {%0,%1,%2,%3}, [%4];" \
                 : "=r"((r)[0]), "=r"((r)[1]), "=r"((r)[2]), "=r"((r)[3])     \
                 : "r"(addr))

#define MMA16(d, a, b0, b1)                                                   \
    asm volatile("mma.sync.aligned.m16n8k16.row.col.f32.f16.f16.f32 "         \
                 "{%0,%1,%2,%3},{%4,%5,%6,%7},{%8,%9},{%0,%1,%2,%3};"         \
                 : "+f"((d)[0]), "+f"((d)[1]), "+f"((d)[2]), "+f"((d)[3])     \
                 : "r"((a)[0]), "r"((a)[1]), "r"((a)[2]), "r"((a)[3]),        \
                   "r"(b0), "r"(b1))

// ---------------------------------------------------------------------------
// fp16 GEMM: C[M,N] = A[M,K] @ BT[N,K]^T. A,BT fp16 row-major, C fp32.
// Block tile 128x128x32; 8 warps, warp tile 32x64; smem rows padded to 80B
// (conflict-free ldmatrix: row*20 words mod 32 distinct over any 8 rows).
// 3-stage cp.async pipeline. Logical A row r -> physical (r/P)*Q + r%P.
// Batched via blockIdx.z with strides aS/bS/cS.
// ---------------------------------------------------------------------------
#define NST 3
#define STG_B 20480          // 128*80 (A) + 128*80 (B)
#define GEMM_SMEM (NST * STG_B)

__global__ __launch_bounds__(256, 2)
void gemm_f16(const __half* __restrict__ A, const __half* __restrict__ BT,
              float* __restrict__ C, int K, int ldc, int P, long Q,
              long long aS, long long bS, long long cS) {
    const uint32_t sb = s2u(dyn_sm);
    const int tid = threadIdx.x, lane = tid & 31, warp = tid >> 5;
    const int wm = warp & 3, wn = warp >> 2;
    const int bn = blockIdx.x, bm = blockIdx.y, bz = blockIdx.z;
    A += aS * bz; BT += bS * bz; C += cS * bz;

    // gmem fill pointers: this thread loads 16B chunks of rows rr and rr+64
    const int rr = tid >> 2, ch = tid & 3;
    long la0 = (long)bm * 128 + rr, la1 = la0 + 64;
    la0 = (la0 / P) * Q + la0 % P;
    la1 = (la1 / P) * Q + la1 % P;
    const __half* a0p = A + la0 * K + ch * 8;
    const __half* a1p = A + la1 * K + ch * 8;
    const __half* b0p = BT + ((long)bn * 128 + rr) * K + ch * 8;
    const __half* b1p = b0p + (long)64 * K;
    const uint32_t dA0 = rr * 80 + ch * 16, dA1 = dA0 + 64 * 80;
    const uint32_t dB0 = 10240 + dA0, dB1 = 10240 + dA1;

    // ldmatrix per-lane addresses (byte offsets within a stage)
    const int rsel = lane & 15, ksel = (lane >> 4) * 8;  // halves
    const uint32_t aoff0 = (uint32_t)(((wm * 32 + rsel) * 40 + ksel) * 2);
    const uint32_t aoff1 = aoff0 + 16 * 80;
    const int nloc = (lane & 7) + ((lane >> 4) << 3), kadd = lane & 8;
    uint32_t boff[4];
#pragma unroll
    for (int p = 0; p < 4; ++p)
        boff[p] = 10240u + (uint32_t)(((wn * 64 + p * 16 + nloc) * 40 + kadd) * 2);

    float acc[2][8][4];
#pragma unroll
    for (int mt = 0; mt < 2; ++mt)
#pragma unroll
        for (int nt = 0; nt < 8; ++nt)
#pragma unroll
            for (int i = 0; i < 4; ++i) acc[mt][nt][i] = 0.0f;

    const int KT = K >> 5;

#define LOADK(kt)                                                   \
    do {                                                            \
        const uint32_t s_ = sb + ((kt) % NST) * STG_B;              \
        cp16(s_ + dA0, a0p + (kt) * 32);                            \
        cp16(s_ + dA1, a1p + (kt) * 32);                            \
        cp16(s_ + dB0, b0p + (kt) * 32);                            \
        cp16(s_ + dB1, b1p + (kt) * 32);                            \
    } while (0)

    LOADK(0); CP_COMMIT();
    LOADK(1); CP_COMMIT();
    LOADK(2); CP_COMMIT();

    for (int kt = 0; kt < KT; ++kt) {
        CP_WAIT2();
        __syncthreads();
        const uint32_t sA = sb + (kt % NST) * STG_B;
#pragma unroll
        for (int ks = 0; ks < 2; ++ks) {
            const uint32_t kb = ks * 32;  // 16 halves
            uint32_t a0[4], a1[4], b[4][4];
            LDSM4(a0, sA + aoff0 + kb);
            LDSM4(a1, sA + aoff1 + kb);
#pragma unroll
            for (int p = 0; p < 4; ++p) LDSM4(b[p], sA + boff[p] + kb);
#pragma unroll
            for (int p = 0; p < 4; ++p) {
                MMA16(acc[0][2 * p],     a0, b[p][0], b[p][1]);
                MMA16(acc[0][2 * p + 1], a0, b[p][2], b[p][3]);
                MMA16(acc[1][2 * p],     a1, b[p][0], b[p][1]);
                MMA16(acc[1][2 * p + 1], a1, b[p][2], b[p][3]);
            }
        }
        __syncthreads();
        if (kt + 3 < KT) LOADK(kt + 3);
        CP_COMMIT();
    }

    const int g = lane >> 2, tg = lane & 3;
#pragma unroll
    for (int mt = 0; mt < 2; ++mt) {
        const int row = bm * 128 + wm * 32 + mt * 16 + g;
#pragma unroll
        for (int nt = 0; nt < 8; ++nt) {
            const int col = bn * 128 + wn * 64 + nt * 8 + 2 * tg;
            *(float2*)(C + (size_t)row * ldc + col) =
                make_float2(acc[mt][nt][0], acc[mt][nt][1]);
            *(float2*)(C + (size_t)(row + 8) * ldc + col) =
                make_float2(acc[mt][nt][2], acc[mt][nt][3]);
        }
    }
#undef LOADK
}

// ---------------------------------------------------------------------------
// prep kernels
// ---------------------------------------------------------------------------
__global__ void round_h(const float* __restrict__ in, __half* __restrict__ out) {
    const int i = blockIdx.x * 256 + threadIdx.x;  // quads
    float4 v = ((const float4*)in)[i];
    __half2 h0 = __floats2half2_rn(v.x, v.y);
    __half2 h1 = __floats2half2_rn(v.z, v.w);
    ((__half2*)out)[2 * i] = h0;
    ((__half2*)out)[2 * i + 1] = h1;
}

// dst[rowoff + c][r] (fp16, ld=ldd) = src[r][c] (fp32, [R][Cc])
__global__ void transpose_h(const float* __restrict__ W, __half* __restrict__ WT,
                            int R, int Cc, int rowoff, int ldd) {
    __shared__ float t[32][33];
    const int c0 = blockIdx.x * 32, r0 = blockIdx.y * 32;
    const int tx = threadIdx.x & 31, ty = threadIdx.x >> 5;
#pragma unroll
    for (int k = 0; k < 32; k += 8)
        t[ty + k][tx] = W[(size_t)(r0 + ty + k) * Cc + c0 + tx];
    __syncthreads();
#pragma unroll
    for (int k = 0; k < 32; k += 8)
        WT[(size_t)(rowoff + c0 + ty + k) * ldd + r0 + tx] = __float2half_rn(t[tx][ty + k]);
}

// ---------------------------------------------------------------------------
// Gates softmax: glog fp32 [262144 rows x 64] -> gates fp16 (same layout).
// 16 lanes per row, 4 consecutive values each.
// ---------------------------------------------------------------------------
__global__ void gates_softmax(const float* __restrict__ gl, __half* __restrict__ g16) {
    const int t = threadIdx.x;
    const size_t row = ((size_t)blockIdx.x * 256 + t) >> 4;
    const int c4 = (t & 15) * 4;
    float4 v = *(const float4*)(gl + row * 64 + c4);
    v.x *= SCALE_F; v.y *= SCALE_F; v.z *= SCALE_F; v.w *= SCALE_F;
    float m = fmaxf(fmaxf(v.x, v.y), fmaxf(v.z, v.w));
#pragma unroll
    for (int o = 8; o > 0; o >>= 1) m = fmaxf(m, __shfl_xor_sync(0xffffffffu, m, o));
    float e0 = expf(v.x - m), e1 = expf(v.y - m), e2 = expf(v.z - m), e3 = expf(v.w - m);
    float s = e0 + e1 + e2 + e3;
#pragma unroll
    for (int o = 8; o > 0; o >>= 1) s += __shfl_xor_sync(0xffffffffu, s, o);
    const float inv = 1.0f / s;
    __half2* p = (__half2*)(g16 + row * 64 + c4);
    p[0] = __floats2half2_rn(e0 * inv, e1 * inv);
    p[1] = __floats2half2_rn(e2 * inv, e3 * inv);
}

// ---------------------------------------------------------------------------
// Latent attention (chunk 0 only): per (b,h) block. kv holds k|v (ld 4096).
// ---------------------------------------------------------------------------
#define ATTN_SMEM_FLOATS (64 * 128 + 128 * 132 + 64 * 128)
#define ATTN_SMEM_BYTES (ATTN_SMEM_FLOATS * 4)

__global__ __launch_bounds__(256)
void attn_kernel(const float* __restrict__ kv, const float* __restrict__ lq,
                 float* __restrict__ attn_out) {
    float* smf = (float*)dyn_sm;
    float* q_s = smf;                 // [64][128]
    float* k_s = smf + 64 * 128;      // [128][132]
    float* w_s = k_s + 128 * 132;     // [64][128]

    const int tid = threadIdx.x;
    const int bh = blockIdx.x;
    const int b = bh >> 4, h = bh & 15;

    for (int i = tid; i < 64 * 128; i += 256) {
        int l = i >> 7, d = i & 127;
        q_s[i] = lq[((size_t)l * 16 + h) * 128 + d];
    }
    const float LOG2_THETA_OVER_HALF = 0.20762050593643188f;  // log2(10000)/64
    for (int p = tid; p < 128 * 64; p += 256) {
        int t = p >> 6, i = p & 63;
        const float* kp = kv + ((size_t)(b * 128 + t)) * 4096 + h * 128 + 2 * i;
        float x0 = kp[0], x1 = kp[1];
        float invf = exp2f(-(float)i * LOG2_THETA_OVER_HALF);
        float ang = (float)t * invf;
        float sn, cs;
        sincosf(ang, &sn, &cs);
        k_s[t * 132 + 2 * i]     = x0 * cs - x1 * sn;
        k_s[t * 132 + 2 * i + 1] = x0 * sn + x1 * cs;
    }
    __syncthreads();

    {
        const int t = tid & 127, lb = tid >> 7;
        const float4* kvv = (const float4*)(k_s + t * 132);
        for (int j = 0; j < 32; ++j) {
            int l = lb + 2 * j;
            const float4* qv = (const float4*)(q_s + l * 128);
            float s = 0.0f;
#pragma unroll
            for (int dd = 0; dd < 32; ++dd) {
                float4 a = qv[dd];
                float4 kk = kvv[dd];
                s += a.x * kk.x + a.y * kk.y + a.z * kk.z + a.w * kk.w;
            }
            s *= SCALE_F;
            if (t > l) s = -1e9f;
            w_s[l * 128 + t] = s;
        }
    }
    __syncthreads();

    {
        const int warp = tid >> 5, lane = tid & 31;
        for (int r = 0; r < 8; ++r) {
            int l = warp * 8 + r;
            float v0 = w_s[l * 128 + lane];
            float v1 = w_s[l * 128 + lane + 32];
            float v2 = w_s[l * 128 + lane + 64];
            float v3 = w_s[l * 128 + lane + 96];
            float m = fmaxf(fmaxf(v0, v1), fmaxf(v2, v3));
#pragma unroll
            for (int o = 16; o > 0; o >>= 1) m = fmaxf(m, __shfl_xor_sync(0xffffffffu, m, o));
            float e0 = expf(v0 - m), e1 = expf(v1 - m), e2 = expf(v2 - m), e3 = expf(v3 - m);
            float s = e0 + e1 + e2 + e3;
#pragma unroll
            for (int o = 16; o > 0; o >>= 1) s += __shfl_xor_sync(0xffffffffu, s, o);
            float inv = 1.0f / s;
            w_s[l * 128 + lane]      = e0 * inv;
            w_s[l * 128 + lane + 32] = e1 * inv;
            w_s[l * 128 + lane + 64] = e2 * inv;
            w_s[l * 128 + lane + 96] = e3 * inv;
        }
    }
    __syncthreads();

    {
        const int d = tid & 127, lb = tid >> 7;
        float acc[32];
#pragma unroll
        for (int j = 0; j < 32; ++j) acc[j] = 0.0f;
        for (int t = 0; t < 128; ++t) {
            float vv = kv[((size_t)(b * 128 + t)) * 4096 + 2048 + h * 128 + d];
#pragma unroll
            for (int j = 0; j < 32; ++j) acc[j] += w_s[(lb + 2 * j) * 128 + t] * vv;
        }
#pragma unroll
        for (int j = 0; j < 32; ++j)
            attn_out[((size_t)bh * 64 + lb + 2 * j) * 128 + d] = acc[j];
    }
}

// ---------------------------------------------------------------------------
// AP: APt[b][n][h*64+l] = sum_d attn[b,h,l,d] * Wp[h*128+d][n]  (fp16 out)
// Block (ntile of 128, bh). smem: attn^T [128][65] + Wp tile [128][128].
// ---------------------------------------------------------------------------
#define AP_SMEM ((128 * 65 + 128 * 128) * 4)

__global__ __launch_bounds__(256)
void ap_kernel(const float* __restrict__ attn, const float* __restrict__ Wp,
               __half* __restrict__ APt) {
    float* smf = (float*)dyn_sm;
    float* aT = smf;              // [d=128][l stride 65]
    float* wp = smf + 128 * 65;   // [d=128][n=128]

    const int tid = threadIdx.x;
    const int bh = blockIdx.y;
    const int b = bh >> 4, h = bh & 15;
    const int n0 = blockIdx.x * 128;

    for (int i = tid; i < 64 * 128; i += 256) {
        int l = i >> 7, d = i & 127;
        aT[d * 65 + l] = attn[(size_t)bh * 8192 + i];
    }
    for (int i = tid; i < 128 * 128; i += 256) {
        int d = i >> 7, c = i & 127;
        wp[i] = Wp[(size_t)(h * 128 + d) * 2048 + n0 + c];
    }
    __syncthreads();

    const int l = tid & 63, ns = (tid >> 6) * 32;
    float acc[32];
#pragma unroll
    for (int i = 0; i < 32; ++i) acc[i] = 0.0f;
    for (int d = 0; d < 128; ++d) {
        const float a = aT[d * 65 + l];
        const float4* w4 = (const float4*)(wp + d * 128 + ns);
#pragma unroll
        for (int i = 0; i < 8; ++i) {
            float4 w = w4[i];
            acc[4 * i]     += a * w.x;
            acc[4 * i + 1] += a * w.y;
            acc[4 * i + 2] += a * w.z;
            acc[4 * i + 3] += a * w.w;
        }
    }
    __half* dst = APt + (size_t)b * 2048 * 1024 + (size_t)h * 64 + l;
#pragma unroll
    for (int i = 0; i < 32; ++i)
        dst[(size_t)(n0 + ns + i) * 1024] = __float2half_rn(acc[i]);
}

// ---------------------------------------------------------------------------
extern "C" void kernel_launch(void* const* d_in, const int* in_sizes, int n_in,
                              void* d_out, int out_size) {
    const float* x  = (const float*)d_in[0];  // [4,4096,2048]
    const float* lq = (const float*)d_in[1];  // [1,64,16,128]
    const float* Wk = (const float*)d_in[2];  // [2048,2048]
    const float* Wv = (const float*)d_in[3];  // [2048,2048]
    const float* Wg = (const float*)d_in[4];  // [2048,1024]
    const float* Wp = (const float*)d_in[5];  // [2048,2048]
    float* out = (float*)d_out;

    __half *x16, *wkvT, *wgT, *g16, *apt;
    float *kvb, *glb, *ab;
    cudaGetSymbolAddress((void**)&x16,  g_x16);
    cudaGetSymbolAddress((void**)&wkvT, g_wkvT);
    cudaGetSymbolAddress((void**)&wgT,  g_wgT);
    cudaGetSymbolAddress((void**)&kvb,  g_kv128);
    cudaGetSymbolAddress((void**)&glb,  g_glog);
    cudaGetSymbolAddress((void**)&g16,  g_gates16);
    cudaGetSymbolAddress((void**)&ab,   g_attn);
    cudaGetSymbolAddress((void**)&apt,  g_APt);

    cudaFuncSetAttribute(gemm_f16, cudaFuncAttributeMaxDynamicSharedMemorySize, GEMM_SMEM);
    cudaFuncSetAttribute(attn_kernel, cudaFuncAttributeMaxDynamicSharedMemorySize,
                         ATTN_SMEM_BYTES);
    cudaFuncSetAttribute(ap_kernel, cudaFuncAttributeMaxDynamicSharedMemorySize, AP_SMEM);

    const int IDP = 1 << 30;  // identity row map

    // prep: x -> fp16; weights -> fp16 transposed ([N][K])
    round_h<<<32768, 256>>>(x, x16);
    transpose_h<<<dim3(64, 64), 256>>>(Wk, wkvT, 2048, 2048, 0, 2048);
    transpose_h<<<dim3(64, 64), 256>>>(Wv, wkvT, 2048, 2048, 2048, 2048);
    transpose_h<<<dim3(32, 64), 256>>>(Wg, wgT, 2048, 1024, 0, 2048);

    // K|V fused GEMM: M=512 (rows (r/128)*4096+r%128), N=4096, K=2048
    gemm_f16<<<dim3(32, 4, 1), 256, GEMM_SMEM>>>(x16, wkvT, kvb, 2048, 4096,
                                                 128, 4096, 0, 0, 0);
    // gate logits: M=16384, N=1024, K=2048
    gemm_f16<<<dim3(8, 128, 1), 256, GEMM_SMEM>>>(x16, wgT, glb, 2048, 1024,
                                                  IDP, 0, 0, 0, 0);
    gates_softmax<<<16384, 256>>>(glb, g16);
    attn_kernel<<<64, 256, ATTN_SMEM_BYTES>>>(kvb, lq, ab);
    ap_kernel<<<dim3(16, 64), 256, AP_SMEM>>>(ab, Wp, apt);
    // out[b] = gates[b] @ AP[b]: M=4096, N=2048, K=1024, batched over 4
    gemm_f16<<<dim3(16, 32, 4), 256, GEMM_SMEM>>>(g16, apt, out, 1024, 2048,
                                                  IDP, 0, 4096LL * 1024, 2048LL * 1024,
                                                  4096LL * 2048);
}

// round 13
// speedup vs baseline: 4.6991x; 1.1234x over previous
#include <cuda_runtime.h>
#include <cuda_fp16.h>
#include <cstdint>
#include <cstddef>

// ---------------------------------------------------------------------------
// MultiLatentAttention — B=4, T=4096, C=2048, H=16, D=128, L=64, CHUNK=128
// Only the first 128 tokens per batch feed the latent attention (mask t<=l).
// Reassociated epilogue: AP[b,h] = attn[b,h] @ Wp_h, out = gates @ AP.
// fp16 m16n8k16 mma GEMMs, ldmatrix, 4-stage cp.async (1 sync per k-tile).
// Gates softmax fused into the gates-GEMM epilogue (each warp's 64-col slice
// is one complete latent group).
// ---------------------------------------------------------------------------

#define SCALE_F 0.08838834764831845f  // 1/sqrt(128)

__device__ __half g_x16[16384 * 2048];     // x rounded to fp16
__device__ __half g_wkvT[4096 * 2048];     // [Wk^T ; Wv^T] fp16, [N][K]
__device__ __half g_wgT[1024 * 2048];      // Wg^T fp16
__device__ float  g_kv128[512 * 4096];     // k (cols 0..2047) | v (2048..4095)
__device__ __half g_gates16[16384 * 1024]; // softmaxed gates fp16
__device__ float  g_attn[64 * 64 * 128];   // attn[bh][l][d]
__device__ __half g_APt[4 * 2048 * 1024];  // per-batch (attn@Wp)^T: [n][h*64+l]

// single dynamic-smem symbol for the whole TU
extern __shared__ char dyn_sm[];

__device__ __forceinline__ uint32_t s2u(const void* p) {
    uint32_t a;
    asm("{ .reg .u64 t; cvta.to.shared.u64 t, %1; cvt.u32.u64 %0, t; }" : "=r"(a) : "l"(p));
    return a;
}
__device__ __forceinline__ void cp16(uint32_t dst, const void* src) {
    asm volatile("cp.async.cg.shared.global [%0], [%1], 16;" :: "r"(dst), "l"(src));
}
#define CP_COMMIT() asm volatile("cp.async.commit_group;" ::: "memory")
#define CP_WAIT2()  asm volatile("cp.async.wait_group 2;" ::: "memory")

#define LDSM4(r, addr)                                                        \
    asm volatile("ldmatrix.sync.aligned.m8n8.x4.shared.b16 {%0,%1,%2,%3}, [%4];" \
                 : "=r"((r)[0]), "=r"((r)[1]), "=r"((r)[2]), "=r"((r)[3])     \
                 : "r"(addr))

#define MMA16(d, a, b0, b1)                                                   \
    asm volatile("mma.sync.aligned.m16n8k16.row.col.f32.f16.f16.f32 "         \
                 "{%0,%1,%2,%3},{%4,%5,%6,%7},{%8,%9},{%0,%1,%2,%3};"         \
                 : "+f"((d)[0]), "+f"((d)[1]), "+f"((d)[2]), "+f"((d)[3])     \
                 : "r"((a)[0]), "r"((a)[1]), "r"((a)[2]), "r"((a)[3]),        \
                   "r"(b0), "r"(b1))

// ---------------------------------------------------------------------------
// fp16 GEMM: C[M,N] = A[M,K] @ BT[N,K]^T. A,BT fp16 row-major.
// Block tile 128x128x32; 8 warps, warp tile 32x64; smem rows padded to 80B.
// 4-stage cp.async pipeline, ONE __syncthreads per k-tile (LOADK(kt+3)
// writes stage (kt-1)%4, already drained by the top-of-iter barrier).
// FUSE==1: row softmax over each 64-col latent group in the epilogue,
// output fp16 (Cv = __half*). FUSE==0: plain fp32 store (Cv = float*).
// Logical A row r -> physical (r/P)*Q + r%P. Batched via blockIdx.z.
// ---------------------------------------------------------------------------
#define NST 4
#define STG_B 20480          // 128*80 (A) + 128*80 (B)
#define GEMM_SMEM (NST * STG_B)   // 81920

template <int FUSE>
__global__ __launch_bounds__(256, 2)
void gemm_f16(const __half* __restrict__ A, const __half* __restrict__ BT,
              void* __restrict__ Cv, int K, int ldc, int P, long Q,
              long long aS, long long bS, long long cS) {
    const uint32_t sb = s2u(dyn_sm);
    const int tid = threadIdx.x, lane = tid & 31, warp = tid >> 5;
    const int wm = warp & 3, wn = warp >> 2;
    const int bn = blockIdx.x, bm = blockIdx.y, bz = blockIdx.z;
    A += aS * bz; BT += bS * bz;

    // gmem fill pointers: this thread loads 16B chunks of rows rr and rr+64
    const int rr = tid >> 2, ch = tid & 3;
    long la0 = (long)bm * 128 + rr, la1 = la0 + 64;
    la0 = (la0 / P) * Q + la0 % P;
    la1 = (la1 / P) * Q + la1 % P;
    const __half* a0p = A + la0 * K + ch * 8;
    const __half* a1p = A + la1 * K + ch * 8;
    const __half* b0p = BT + ((long)bn * 128 + rr) * K + ch * 8;
    const __half* b1p = b0p + (long)64 * K;
    const uint32_t dA0 = rr * 80 + ch * 16, dA1 = dA0 + 64 * 80;
    const uint32_t dB0 = 10240 + dA0, dB1 = 10240 + dA1;

    // ldmatrix per-lane addresses (byte offsets within a stage)
    const int rsel = lane & 15, ksel = (lane >> 4) * 8;  // halves
    const uint32_t aoff0 = (uint32_t)(((wm * 32 + rsel) * 40 + ksel) * 2);
    const uint32_t aoff1 = aoff0 + 16 * 80;
    const int nloc = (lane & 7) + ((lane >> 4) << 3), kadd = lane & 8;
    uint32_t boff[4];
#pragma unroll
    for (int p = 0; p < 4; ++p)
        boff[p] = 10240u + (uint32_t)(((wn * 64 + p * 16 + nloc) * 40 + kadd) * 2);

    float acc[2][8][4];
#pragma unroll
    for (int mt = 0; mt < 2; ++mt)
#pragma unroll
        for (int nt = 0; nt < 8; ++nt)
#pragma unroll
            for (int i = 0; i < 4; ++i) acc[mt][nt][i] = 0.0f;

    const int KT = K >> 5;

#define LOADK(kt)                                                   \
    do {                                                            \
        const uint32_t s_ = sb + ((kt) % NST) * STG_B;              \
        cp16(s_ + dA0, a0p + (kt) * 32);                            \
        cp16(s_ + dA1, a1p + (kt) * 32);                            \
        cp16(s_ + dB0, b0p + (kt) * 32);                            \
        cp16(s_ + dB1, b1p + (kt) * 32);                            \
    } while (0)

    LOADK(0); CP_COMMIT();
    LOADK(1); CP_COMMIT();
    LOADK(2); CP_COMMIT();

    for (int kt = 0; kt < KT; ++kt) {
        CP_WAIT2();
        __syncthreads();
        const uint32_t sA = sb + (kt % NST) * STG_B;
#pragma unroll
        for (int ks = 0; ks < 2; ++ks) {
            const uint32_t kb = ks * 32;  // 16 halves
            uint32_t a0[4], a1[4], b[4][4];
            LDSM4(a0, sA + aoff0 + kb);
            LDSM4(a1, sA + aoff1 + kb);
#pragma unroll
            for (int p = 0; p < 4; ++p) LDSM4(b[p], sA + boff[p] + kb);
#pragma unroll
            for (int p = 0; p < 4; ++p) {
                MMA16(acc[0][2 * p],     a0, b[p][0], b[p][1]);
                MMA16(acc[0][2 * p + 1], a0, b[p][2], b[p][3]);
                MMA16(acc[1][2 * p],     a1, b[p][0], b[p][1]);
                MMA16(acc[1][2 * p + 1], a1, b[p][2], b[p][3]);
            }
        }
        if (kt + 3 < KT) LOADK(kt + 3);
        CP_COMMIT();
    }

    const int g = lane >> 2, tg = lane & 3;
    if (FUSE) {
        // Row softmax over this warp's 64-col group (cols bn*128 + wn*64 + ..).
        // Per (mt, half): 16 values across nt; reduce across the 4 tg lanes.
        __half* C16 = (__half*)Cv + cS * bz;
#pragma unroll
        for (int mt = 0; mt < 2; ++mt) {
#pragma unroll
            for (int half = 0; half < 2; ++half) {
                const int row = bm * 128 + wm * 32 + mt * 16 + g + half * 8;
                float v[16];
#pragma unroll
                for (int nt = 0; nt < 8; ++nt) {
                    v[2 * nt]     = acc[mt][nt][2 * half]     * SCALE_F;
                    v[2 * nt + 1] = acc[mt][nt][2 * half + 1] * SCALE_F;
                }
                float m = v[0];
#pragma unroll
                for (int i = 1; i < 16; ++i) m = fmaxf(m, v[i]);
                m = fmaxf(m, __shfl_xor_sync(0xffffffffu, m, 1));
                m = fmaxf(m, __shfl_xor_sync(0xffffffffu, m, 2));
                float s = 0.0f;
#pragma unroll
                for (int i = 0; i < 16; ++i) { v[i] = __expf(v[i] - m); s += v[i]; }
                s += __shfl_xor_sync(0xffffffffu, s, 1);
                s += __shfl_xor_sync(0xffffffffu, s, 2);
                const float inv = 1.0f / s;
                __half* rp = C16 + (size_t)row * ldc + bn * 128 + wn * 64 + 2 * tg;
#pragma unroll
                for (int nt = 0; nt < 8; ++nt)
                    *(__half2*)(rp + nt * 8) =
                        __floats2half2_rn(v[2 * nt] * inv, v[2 * nt + 1] * inv);
            }
        }
    } else {
        float* C = (float*)Cv + cS * bz;
#pragma unroll
        for (int mt = 0; mt < 2; ++mt) {
            const int row = bm * 128 + wm * 32 + mt * 16 + g;
#pragma unroll
            for (int nt = 0; nt < 8; ++nt) {
                const int col = bn * 128 + wn * 64 + nt * 8 + 2 * tg;
                *(float2*)(C + (size_t)row * ldc + col) =
                    make_float2(acc[mt][nt][0], acc[mt][nt][1]);
                *(float2*)(C + (size_t)(row + 8) * ldc + col) =
                    make_float2(acc[mt][nt][2], acc[mt][nt][3]);
            }
        }
    }
#undef LOADK
}

// ---------------------------------------------------------------------------
// prep kernels
// ---------------------------------------------------------------------------
__global__ void round_h(const float* __restrict__ in, __half* __restrict__ out) {
    const int i = blockIdx.x * 256 + threadIdx.x;  // quads
    float4 v = ((const float4*)in)[i];
    ((__half2*)out)[2 * i]     = __floats2half2_rn(v.x, v.y);
    ((__half2*)out)[2 * i + 1] = __floats2half2_rn(v.z, v.w);
}

// dst[rowoff + c][r] (fp16, ld=ldd) = src[r][c] (fp32, [R][Cc])
__global__ void transpose_h(const float* __restrict__ W, __half* __restrict__ WT,
                            int R, int Cc, int rowoff, int ldd) {
    __shared__ float t[32][33];
    const int c0 = blockIdx.x * 32, r0 = blockIdx.y * 32;
    const int tx = threadIdx.x & 31, ty = threadIdx.x >> 5;
#pragma unroll
    for (int k = 0; k < 32; k += 8)
        t[ty + k][tx] = W[(size_t)(r0 + ty + k) * Cc + c0 + tx];
    __syncthreads();
#pragma unroll
    for (int k = 0; k < 32; k += 8)
        WT[(size_t)(rowoff + c0 + ty + k) * ldd + r0 + tx] = __float2half_rn(t[tx][ty + k]);
}

// ---------------------------------------------------------------------------
// Latent attention (chunk 0 only): per (b,h) block. kv holds k|v (ld 4096).
// ---------------------------------------------------------------------------
#define ATTN_SMEM_FLOATS (64 * 128 + 128 * 132 + 64 * 128)
#define ATTN_SMEM_BYTES (ATTN_SMEM_FLOATS * 4)

__global__ __launch_bounds__(256)
void attn_kernel(const float* __restrict__ kv, const float* __restrict__ lq,
                 float* __restrict__ attn_out) {
    float* smf = (float*)dyn_sm;
    float* q_s = smf;                 // [64][128]
    float* k_s = smf + 64 * 128;      // [128][132]
    float* w_s = k_s + 128 * 132;     // [64][128]

    const int tid = threadIdx.x;
    const int bh = blockIdx.x;
    const int b = bh >> 4, h = bh & 15;

    for (int i = tid; i < 64 * 128; i += 256) {
        int l = i >> 7, d = i & 127;
        q_s[i] = lq[((size_t)l * 16 + h) * 128 + d];
    }
    const float LOG2_THETA_OVER_HALF = 0.20762050593643188f;  // log2(10000)/64
    for (int p = tid; p < 128 * 64; p += 256) {
        int t = p >> 6, i = p & 63;
        const float* kp = kv + ((size_t)(b * 128 + t)) * 4096 + h * 128 + 2 * i;
        float x0 = kp[0], x1 = kp[1];
        float invf = exp2f(-(float)i * LOG2_THETA_OVER_HALF);
        float ang = (float)t * invf;
        float sn, cs;
        sincosf(ang, &sn, &cs);
        k_s[t * 132 + 2 * i]     = x0 * cs - x1 * sn;
        k_s[t * 132 + 2 * i + 1] = x0 * sn + x1 * cs;
    }
    __syncthreads();

    {
        const int t = tid & 127, lb = tid >> 7;
        const float4* kvv = (const float4*)(k_s + t * 132);
        for (int j = 0; j < 32; ++j) {
            int l = lb + 2 * j;
            const float4* qv = (const float4*)(q_s + l * 128);
            float s = 0.0f;
#pragma unroll
            for (int dd = 0; dd < 32; ++dd) {
                float4 a = qv[dd];
                float4 kk = kvv[dd];
                s += a.x * kk.x + a.y * kk.y + a.z * kk.z + a.w * kk.w;
            }
            s *= SCALE_F;
            if (t > l) s = -1e9f;
            w_s[l * 128 + t] = s;
        }
    }
    __syncthreads();

    {
        const int warp = tid >> 5, lane = tid & 31;
        for (int r = 0; r < 8; ++r) {
            int l = warp * 8 + r;
            float v0 = w_s[l * 128 + lane];
            float v1 = w_s[l * 128 + lane + 32];
            float v2 = w_s[l * 128 + lane + 64];
            float v3 = w_s[l * 128 + lane + 96];
            float m = fmaxf(fmaxf(v0, v1), fmaxf(v2, v3));
#pragma unroll
            for (int o = 16; o > 0; o >>= 1) m = fmaxf(m, __shfl_xor_sync(0xffffffffu, m, o));
            float e0 = __expf(v0 - m), e1 = __expf(v1 - m);
            float e2 = __expf(v2 - m), e3 = __expf(v3 - m);
            float s = e0 + e1 + e2 + e3;
#pragma unroll
            for (int o = 16; o > 0; o >>= 1) s += __shfl_xor_sync(0xffffffffu, s, o);
            float inv = 1.0f / s;
            w_s[l * 128 + lane]      = e0 * inv;
            w_s[l * 128 + lane + 32] = e1 * inv;
            w_s[l * 128 + lane + 64] = e2 * inv;
            w_s[l * 128 + lane + 96] = e3 * inv;
        }
    }
    __syncthreads();

    {
        const int d = tid & 127, lb = tid >> 7;
        float acc[32];
#pragma unroll
        for (int j = 0; j < 32; ++j) acc[j] = 0.0f;
        for (int t = 0; t < 128; ++t) {
            float vv = kv[((size_t)(b * 128 + t)) * 4096 + 2048 + h * 128 + d];
#pragma unroll
            for (int j = 0; j < 32; ++j) acc[j] += w_s[(lb + 2 * j) * 128 + t] * vv;
        }
#pragma unroll
        for (int j = 0; j < 32; ++j)
            attn_out[((size_t)bh * 64 + lb + 2 * j) * 128 + d] = acc[j];
    }
}

// ---------------------------------------------------------------------------
// AP: APt[b][n][h*64+l] = sum_d attn[b,h,l,d] * Wp[h*128+d][n]  (fp16 out)
// Block (ntile of 128, bh). smem: attn^T [128][65] + Wp tile [128][128].
// ---------------------------------------------------------------------------
#define AP_SMEM ((128 * 65 + 128 * 128) * 4)

__global__ __launch_bounds__(256)
void ap_kernel(const float* __restrict__ attn, const float* __restrict__ Wp,
               __half* __restrict__ APt) {
    float* smf = (float*)dyn_sm;
    float* aT = smf;              // [d=128][l stride 65]
    float* wp = smf + 128 * 65;   // [d=128][n=128]

    const int tid = threadIdx.x;
    const int bh = blockIdx.y;
    const int b = bh >> 4, h = bh & 15;
    const int n0 = blockIdx.x * 128;

    for (int i = tid; i < 64 * 128; i += 256) {
        int l = i >> 7, d = i & 127;
        aT[d * 65 + l] = attn[(size_t)bh * 8192 + i];
    }
    for (int i = tid; i < 128 * 128; i += 256) {
        int d = i >> 7, c = i & 127;
        wp[i] = Wp[(size_t)(h * 128 + d) * 2048 + n0 + c];
    }
    __syncthreads();

    const int l = tid & 63, ns = (tid >> 6) * 32;
    float acc[32];
#pragma unroll
    for (int i = 0; i < 32; ++i) acc[i] = 0.0f;
    for (int d = 0; d < 128; ++d) {
        const float a = aT[d * 65 + l];
        const float4* w4 = (const float4*)(wp + d * 128 + ns);
#pragma unroll
        for (int i = 0; i < 8; ++i) {
            float4 w = w4[i];
            acc[4 * i]     += a * w.x;
            acc[4 * i + 1] += a * w.y;
            acc[4 * i + 2] += a * w.z;
            acc[4 * i + 3] += a * w.w;
        }
    }
    __half* dst = APt + (size_t)b * 2048 * 1024 + (size_t)h * 64 + l;
#pragma unroll
    for (int i = 0; i < 32; ++i)
        dst[(size_t)(n0 + ns + i) * 1024] = __float2half_rn(acc[i]);
}

// ---------------------------------------------------------------------------
extern "C" void kernel_launch(void* const* d_in, const int* in_sizes, int n_in,
                              void* d_out, int out_size) {
    const float* x  = (const float*)d_in[0];  // [4,4096,2048]
    const float* lq = (const float*)d_in[1];  // [1,64,16,128]
    const float* Wk = (const float*)d_in[2];  // [2048,2048]
    const float* Wv = (const float*)d_in[3];  // [2048,2048]
    const float* Wg = (const float*)d_in[4];  // [2048,1024]
    const float* Wp = (const float*)d_in[5];  // [2048,2048]
    float* out = (float*)d_out;

    __half *x16, *wkvT, *wgT, *g16, *apt;
    float *kvb, *ab;
    cudaGetSymbolAddress((void**)&x16,  g_x16);
    cudaGetSymbolAddress((void**)&wkvT, g_wkvT);
    cudaGetSymbolAddress((void**)&wgT,  g_wgT);
    cudaGetSymbolAddress((void**)&kvb,  g_kv128);
    cudaGetSymbolAddress((void**)&g16,  g_gates16);
    cudaGetSymbolAddress((void**)&ab,   g_attn);
    cudaGetSymbolAddress((void**)&apt,  g_APt);

    cudaFuncSetAttribute(gemm_f16<0>, cudaFuncAttributeMaxDynamicSharedMemorySize, GEMM_SMEM);
    cudaFuncSetAttribute(gemm_f16<1>, cudaFuncAttributeMaxDynamicSharedMemorySize, GEMM_SMEM);
    cudaFuncSetAttribute(attn_kernel, cudaFuncAttributeMaxDynamicSharedMemorySize,
                         ATTN_SMEM_BYTES);
    cudaFuncSetAttribute(ap_kernel, cudaFuncAttributeMaxDynamicSharedMemorySize, AP_SMEM);

    const int IDP = 1 << 30;  // identity row map

    // prep: x -> fp16; weights -> fp16 transposed ([N][K])
    round_h<<<32768, 256>>>(x, x16);
    transpose_h<<<dim3(64, 64), 256>>>(Wk, wkvT, 2048, 2048, 0, 2048);
    transpose_h<<<dim3(64, 64), 256>>>(Wv, wkvT, 2048, 2048, 2048, 2048);
    transpose_h<<<dim3(32, 64), 256>>>(Wg, wgT, 2048, 1024, 0, 2048);

    // K|V fused GEMM: M=512 (rows (r/128)*4096+r%128), N=4096, K=2048
    gemm_f16<0><<<dim3(32, 4, 1), 256, GEMM_SMEM>>>(x16, wkvT, kvb, 2048, 4096,
                                                    128, 4096, 0, 0, 0);
    // gate logits + fused softmax -> fp16 gates: M=16384, N=1024, K=2048
    gemm_f16<1><<<dim3(8, 128, 1), 256, GEMM_SMEM>>>(x16, wgT, g16, 2048, 1024,
                                                     IDP, 0, 0, 0, 0);
    attn_kernel<<<64, 256, ATTN_SMEM_BYTES>>>(kvb, lq, ab);
    ap_kernel<<<dim3(16, 64), 256, AP_SMEM>>>(ab, Wp, apt);
    // out[b] = gates[b] @ AP[b]: M=4096, N=2048, K=1024, batched over 4
    gemm_f16<0><<<dim3(16, 32, 4), 256, GEMM_SMEM>>>(g16, apt, out, 1024, 2048,
                                                     IDP, 0, 4096LL * 1024, 2048LL * 1024,
                                                     4096LL * 2048);
}